// round 1
// baseline (speedup 1.0000x reference)
#include <cuda_runtime.h>

namespace {
constexpr int C_ = 150;
constexpr int H_ = 384;
constexpr int W_ = 512;
constexpr int HW_ = H_ * W_;
constexpr int B_ = 4;
constexpr int NPIX = B_ * HW_;          // 786432
constexpr int NGRP = NPIX / 4;          // 196608 groups of 4 pixels
constexpr int THREADS = 256;
constexpr int BLOCKS = NGRP / THREADS;  // 768
}

__device__ double g_loss_sum;
__device__ unsigned int g_valid_cnt;

__global__ void wcel_init() {
    g_loss_sum = 0.0;
    g_valid_cnt = 0u;
}

__global__ __launch_bounds__(THREADS) void wcel_main(
    const float* __restrict__ pred,
    const int*   __restrict__ gt_bins,
    const float* __restrict__ mask,
    const float* __restrict__ weight)
{
    const int q  = blockIdx.x * THREADS + threadIdx.x;  // pixel-group id
    const int p0 = q << 2;                              // first pixel of group
    const int b  = p0 / HW_;
    const int hw = p0 - b * HW_;

    // x[b, c, hw..hw+3] : float4 per channel, channel stride HW_/4 float4s
    const float4* __restrict__ xp =
        reinterpret_cast<const float4*>(pred) + (((size_t)b * C_ * HW_ + hw) >> 2);
    const size_t cstride = HW_ >> 2;

    const int4 g = *reinterpret_cast<const int4*>(gt_bins + p0);
    const float* __restrict__ w0 = weight + (size_t)g.x * C_;
    const float* __restrict__ w1 = weight + (size_t)g.y * C_;
    const float* __restrict__ w2 = weight + (size_t)g.z * C_;
    const float* __restrict__ w3 = weight + (size_t)g.w * C_;

    float s0 = 0.f, s1 = 0.f, s2 = 0.f, s3 = 0.f;   // sum exp(x)
    float d0 = 0.f, d1 = 0.f, d2 = 0.f, d3 = 0.f;   // dot(w_row, x)
    float r0 = 0.f, r1 = 0.f, r2 = 0.f, r3 = 0.f;   // row-sum of w

    #pragma unroll 5
    for (int c = 0; c < C_; ++c) {
        const float4 x = __ldg(xp + (size_t)c * cstride);
        const float a0 = __ldg(w0 + c);
        const float a1 = __ldg(w1 + c);
        const float a2 = __ldg(w2 + c);
        const float a3 = __ldg(w3 + c);
        s0 += __expf(x.x); s1 += __expf(x.y);
        s2 += __expf(x.z); s3 += __expf(x.w);
        d0 = fmaf(a0, x.x, d0); d1 = fmaf(a1, x.y, d1);
        d2 = fmaf(a2, x.z, d2); d3 = fmaf(a3, x.w, d3);
        r0 += a0; r1 += a1; r2 += a2; r3 += a3;
    }

    const float4 m = *reinterpret_cast<const float4*>(mask + p0);
    float loc = 0.f;
    int   vc  = 0;
    loc += m.x * (d0 - __logf(s0) * r0); vc += (m.x > 0.f);
    loc += m.y * (d1 - __logf(s1) * r1); vc += (m.y > 0.f);
    loc += m.z * (d2 - __logf(s2) * r2); vc += (m.z > 0.f);
    loc += m.w * (d3 - __logf(s3) * r3); vc += (m.w > 0.f);

    // Warp reduction
    #pragma unroll
    for (int o = 16; o > 0; o >>= 1) {
        loc += __shfl_down_sync(0xffffffffu, loc, o);
        vc  += __shfl_down_sync(0xffffffffu, vc,  o);
    }

    __shared__ float s_loc[THREADS / 32];
    __shared__ int   s_vc[THREADS / 32];
    const int lane = threadIdx.x & 31;
    const int wid  = threadIdx.x >> 5;
    if (lane == 0) { s_loc[wid] = loc; s_vc[wid] = vc; }
    __syncthreads();

    if (wid == 0) {
        loc = (lane < (THREADS / 32)) ? s_loc[lane] : 0.f;
        vc  = (lane < (THREADS / 32)) ? s_vc[lane]  : 0;
        #pragma unroll
        for (int o = (THREADS / 64); o > 0; o >>= 1) {
            loc += __shfl_down_sync(0xffffffffu, loc, o);
            vc  += __shfl_down_sync(0xffffffffu, vc,  o);
        }
        if (lane == 0) {
            atomicAdd(&g_loss_sum, (double)loc);
            atomicAdd(&g_valid_cnt, (unsigned)vc);
        }
    }
}

__global__ void wcel_final(float* __restrict__ out) {
    out[0] = (float)(-g_loss_sum / (double)g_valid_cnt);
}

extern "C" void kernel_launch(void* const* d_in, const int* in_sizes, int n_in,
                              void* d_out, int out_size) {
    const float* pred   = (const float*)d_in[0];   // pred_logit [B,C,H,W] f32
    const int*   gbins  = (const int*)  d_in[1];   // gt_bins    [B,1,H,W] i32
    // d_in[2] = gt (unused by the loss math)
    const float* mask   = (const float*)d_in[3];   // mask       [B,1,H,W] f32
    const float* weight = (const float*)d_in[4];   // weight     [C,C]     f32

    wcel_init<<<1, 1>>>();
    wcel_main<<<BLOCKS, THREADS>>>(pred, gbins, mask, weight);
    wcel_final<<<1, 1>>>((float*)d_out);
}

// round 2
// speedup vs baseline: 2.0681x; 2.0681x over previous
#include <cuda_runtime.h>

namespace {
constexpr int C_      = 150;
constexpr int H_      = 384;
constexpr int W_      = 512;
constexpr int HW_     = H_ * W_;
constexpr int B_      = 4;
constexpr int NPIX    = B_ * HW_;       // 786432
constexpr int NGRP    = NPIX / 4;       // 196608 pixel-groups of 4
constexpr int THREADS = 256;
constexpr int BLOCKS  = 296;            // 2 CTAs/SM persistent
constexpr int WPAD    = 154;            // row pad: 77 (8B pairs) coprime with 16
constexpr int SMEM_W  = C_ * WPAD;      // 23100 floats
constexpr int SMEM_BYTES = (SMEM_W + C_) * 4;   // + rowsum; ~92.7 KB
}

__device__ double       g_sum;      // zero-initialized
__device__ unsigned int g_vcnt;
__device__ unsigned int g_ticket;

__global__ __launch_bounds__(THREADS, 2) void wcel_fused(
    const float* __restrict__ pred,
    const int*   __restrict__ gt_bins,
    const float* __restrict__ mask,
    const float* __restrict__ weight,
    float*       __restrict__ out)
{
    extern __shared__ float sm[];
    float* sw  = sm;             // [C_][WPAD]
    float* srs = sm + SMEM_W;    // [C_] row sums

    const int tid = threadIdx.x;

    // Stage weight table into padded smem (coalesced gmem read, L2-resident)
    for (int i = tid; i < C_ * C_; i += THREADS) {
        const int r = i / C_;
        const int c = i - r * C_;
        sw[r * WPAD + c] = weight[i];
    }
    __syncthreads();
    // Row sums
    for (int r = tid; r < C_; r += THREADS) {
        float s = 0.f;
        const float* row = sw + r * WPAD;
        #pragma unroll 6
        for (int c = 0; c < C_; ++c) s += row[c];
        srs[r] = s;
    }
    __syncthreads();

    const size_t cstride = HW_ >> 2;   // channel stride in float4s
    float loc = 0.f;
    int   vc  = 0;

    for (int q = blockIdx.x * THREADS + tid; q < NGRP; q += BLOCKS * THREADS) {
        const int p0 = q << 2;
        const int b  = p0 / HW_;
        const int hw = p0 - b * HW_;

        const float4* __restrict__ xp =
            reinterpret_cast<const float4*>(pred) + (((size_t)b * C_ * HW_ + hw) >> 2);

        const int4 g = *reinterpret_cast<const int4*>(gt_bins + p0);
        const float* __restrict__ w0 = sw + g.x * WPAD;
        const float* __restrict__ w1 = sw + g.y * WPAD;
        const float* __restrict__ w2 = sw + g.z * WPAD;
        const float* __restrict__ w3 = sw + g.w * WPAD;

        float s0 = 0.f, s1 = 0.f, s2 = 0.f, s3 = 0.f;   // sum exp(x)
        float d0 = 0.f, d1 = 0.f, d2 = 0.f, d3 = 0.f;   // dot(w_row, x)

        #pragma unroll 5
        for (int c2 = 0; c2 < C_ / 2; ++c2) {
            const int c = c2 * 2;
            const float4 xa = __ldg(xp + (size_t)c * cstride);
            const float4 xb = __ldg(xp + (size_t)(c + 1) * cstride);
            const float2 a0 = *reinterpret_cast<const float2*>(w0 + c);
            const float2 a1 = *reinterpret_cast<const float2*>(w1 + c);
            const float2 a2 = *reinterpret_cast<const float2*>(w2 + c);
            const float2 a3 = *reinterpret_cast<const float2*>(w3 + c);

            s0 += __expf(xa.x); s0 += __expf(xb.x);
            s1 += __expf(xa.y); s1 += __expf(xb.y);
            s2 += __expf(xa.z); s2 += __expf(xb.z);
            s3 += __expf(xa.w); s3 += __expf(xb.w);

            d0 = fmaf(a0.x, xa.x, d0); d0 = fmaf(a0.y, xb.x, d0);
            d1 = fmaf(a1.x, xa.y, d1); d1 = fmaf(a1.y, xb.y, d1);
            d2 = fmaf(a2.x, xa.z, d2); d2 = fmaf(a2.y, xb.z, d2);
            d3 = fmaf(a3.x, xa.w, d3); d3 = fmaf(a3.y, xb.w, d3);
        }

        const float4 m = *reinterpret_cast<const float4*>(mask + p0);
        loc += m.x * (d0 - __logf(s0) * srs[g.x]); vc += (m.x > 0.f);
        loc += m.y * (d1 - __logf(s1) * srs[g.y]); vc += (m.y > 0.f);
        loc += m.z * (d2 - __logf(s2) * srs[g.z]); vc += (m.z > 0.f);
        loc += m.w * (d3 - __logf(s3) * srs[g.w]); vc += (m.w > 0.f);
    }

    // Block reduction
    #pragma unroll
    for (int o = 16; o > 0; o >>= 1) {
        loc += __shfl_down_sync(0xffffffffu, loc, o);
        vc  += __shfl_down_sync(0xffffffffu, vc,  o);
    }
    __shared__ float s_loc[THREADS / 32];
    __shared__ int   s_vc[THREADS / 32];
    const int lane = tid & 31;
    const int wid  = tid >> 5;
    if (lane == 0) { s_loc[wid] = loc; s_vc[wid] = vc; }
    __syncthreads();

    if (tid == 0) {
        float bl = 0.f; int bv = 0;
        #pragma unroll
        for (int i = 0; i < THREADS / 32; ++i) { bl += s_loc[i]; bv += s_vc[i]; }
        atomicAdd(&g_sum, (double)bl);
        atomicAdd(&g_vcnt, (unsigned)bv);
        __threadfence();
        const unsigned old = atomicInc(&g_ticket, BLOCKS - 1);   // wraps to 0
        if (old == BLOCKS - 1) {
            // last block: finalize and self-reset for the next graph replay
            out[0] = (float)(-g_sum / (double)g_vcnt);
            g_sum  = 0.0;
            g_vcnt = 0u;
        }
    }
}

extern "C" void kernel_launch(void* const* d_in, const int* in_sizes, int n_in,
                              void* d_out, int out_size) {
    const float* pred   = (const float*)d_in[0];   // pred_logit [B,C,H,W] f32
    const int*   gbins  = (const int*)  d_in[1];   // gt_bins    [B,1,H,W] i32
    // d_in[2] = gt (unused by the loss math)
    const float* mask   = (const float*)d_in[3];   // mask       [B,1,H,W] f32
    const float* weight = (const float*)d_in[4];   // weight     [C,C]     f32

    static bool attr_set = false;
    if (!attr_set) {
        cudaFuncSetAttribute(wcel_fused,
                             cudaFuncAttributeMaxDynamicSharedMemorySize,
                             SMEM_BYTES);
        attr_set = true;
    }
    wcel_fused<<<BLOCKS, THREADS, SMEM_BYTES>>>(pred, gbins, mask, weight,
                                                (float*)d_out);
}